// round 8
// baseline (speedup 1.0000x reference)
#include <cuda_runtime.h>
#include <cuda_bf16.h>

#define NN   13824
#define BB   256
#define DIM  512
#define OD   1000
#define ODP  1024
#define SK   9
#define KC   (NN / SK)
#define CUBE 24

// ---- stencil smem geometry (y-row padding, all accesses 8/16B aligned) ----
#define SITE 16
#define H_YS (26 * SITE + 16)      // 432 floats; %32 banks = 16 -> LDS.64 conflict-free
#define H_ZS (6 * H_YS)            // 2592
#define HALO_F (4 * H_ZS)          // 10368 floats
#define W_RS 648                   // 3*9*24; %32 = 8 -> ry broadcast banks distinct
#define WSH_F (8 * W_RS)           // 5184 floats
#define STEP_SMEM ((HALO_F + WSH_F) * 4)   // 62208 B -> 3 CTA/SM

// ---- GEMM smem geometry (bf16 units) ----
#define AS_STRIDE 72
#define BS_STRIDE 136
#define AS_PLANE  (128 * AS_STRIDE)
#define BS_PLANE  (64 * BS_STRIDE)
#define BS_OFF    (2 * AS_PLANE)
#define STG_UNITS (2 * AS_PLANE + 2 * BS_PLANE)
#define STG_BYTES (STG_UNITS * 2)
#define GEMM_SMEM (2 * STG_BYTES)

// ---------------- device scratch ----------------
__device__ float g_xp[NN * BB];
__device__ float g_h[2][NN * BB];
__device__ float g_part[SK * BB * ODP];
__device__ __nv_bfloat16 g_WinH[NN * DIM], g_WinL[NN * DIM];
__device__ __nv_bfloat16 g_xTH[DIM * BB],  g_xTL[DIM * BB];
__device__ __nv_bfloat16 g_WoH[OD * NN],   g_WoL[OD * NN];
__device__ __nv_bfloat16 g_hH[NN * BB],    g_hL[NN * BB];

__device__ __forceinline__ float tanh_acc(float x) {
    x = fminf(15.0f, fmaxf(-15.0f, x));
    float e = __expf(2.0f * x);
    return __fdividef(e - 1.0f, e + 1.0f);
}

// ---------------- split conversion ----------------
__global__ __launch_bounds__(256) void split_kernel(const float* __restrict__ s,
                                                    __nv_bfloat16* __restrict__ hi,
                                                    __nv_bfloat16* __restrict__ lo, int n4) {
    int i = blockIdx.x * 256 + threadIdx.x;
    if (i >= n4) return;
    float4 v = *(const float4*)(s + i * 4);
    __nv_bfloat16 h0 = __float2bfloat16_rn(v.x), h1 = __float2bfloat16_rn(v.y);
    __nv_bfloat16 h2 = __float2bfloat16_rn(v.z), h3 = __float2bfloat16_rn(v.w);
    __nv_bfloat162 H0 = {h0, h1}, H1 = {h2, h3};
    *(__nv_bfloat162*)(hi + i * 4) = H0;
    *(__nv_bfloat162*)(hi + i * 4 + 2) = H1;
    __nv_bfloat162 L0 = {__float2bfloat16_rn(v.x - __bfloat162float(h0)),
                         __float2bfloat16_rn(v.y - __bfloat162float(h1))};
    __nv_bfloat162 L1 = {__float2bfloat16_rn(v.z - __bfloat162float(h2)),
                         __float2bfloat16_rn(v.w - __bfloat162float(h3))};
    *(__nv_bfloat162*)(lo + i * 4) = L0;
    *(__nv_bfloat162*)(lo + i * 4 + 2) = L1;
}

__global__ __launch_bounds__(256) void split_xT_kernel(const float* __restrict__ x) {
    __shared__ float t[32][33];
    int bx = blockIdx.x * 32, kx = blockIdx.y * 32;
    int tx = threadIdx.x & 31, ty = threadIdx.x >> 5;
#pragma unroll
    for (int j = ty; j < 32; j += 8)
        t[j][tx] = x[(size_t)(bx + j) * DIM + kx + tx];
    __syncthreads();
#pragma unroll
    for (int j = ty; j < 32; j += 8) {
        float v = t[tx][j];
        __nv_bfloat16 h = __float2bfloat16_rn(v);
        size_t o = (size_t)(kx + j) * BB + bx + tx;
        g_xTH[o] = h;
        g_xTL[o] = __float2bfloat16_rn(v - __bfloat162float(h));
    }
}

// ---------------- mma helpers ----------------
__device__ __forceinline__ void ldsm4(unsigned* r, unsigned addr) {
    asm volatile("ldmatrix.sync.aligned.m8n8.x4.shared.b16 {%0,%1,%2,%3},[%4];"
                 : "=r"(r[0]), "=r"(r[1]), "=r"(r[2]), "=r"(r[3]) : "r"(addr));
}
__device__ __forceinline__ void ldsm4t(unsigned* r, unsigned addr) {
    asm volatile("ldmatrix.sync.aligned.m8n8.x4.trans.shared.b16 {%0,%1,%2,%3},[%4];"
                 : "=r"(r[0]), "=r"(r[1]), "=r"(r[2]), "=r"(r[3]) : "r"(addr));
}
__device__ __forceinline__ void mma_bf16(float* c, const unsigned* a, const unsigned* b) {
    asm volatile("mma.sync.aligned.m16n8k16.row.col.f32.bf16.bf16.f32 "
                 "{%0,%1,%2,%3},{%4,%5,%6,%7},{%8,%9},{%0,%1,%2,%3};"
                 : "+f"(c[0]), "+f"(c[1]), "+f"(c[2]), "+f"(c[3])
                 : "r"(a[0]), "r"(a[1]), "r"(a[2]), "r"(a[3]), "r"(b[0]), "r"(b[1]));
}
__device__ __forceinline__ void cpa16(unsigned s, const void* g, int zs) {
    asm volatile("cp.async.ca.shared.global [%0],[%1],16,%2;" :: "r"(s), "l"(g), "r"(zs));
}
__device__ __forceinline__ void cpa_commit() {
    asm volatile("cp.async.commit_group;" ::: "memory");
}
__device__ __forceinline__ void cpa_wait1() {
    asm volatile("cp.async.wait_group 1;" ::: "memory");
}
__device__ __forceinline__ void cpa_wait0() {
    asm volatile("cp.async.wait_group 0;" ::: "memory");
}

// ---------------- split-precision bf16 MMA GEMM, 2-stage pipeline ----------------
template<int MODE>
__global__ __launch_bounds__(256) void mma_gemm(
    const __nv_bfloat16* __restrict__ Ah, const __nv_bfloat16* __restrict__ Al,
    const __nv_bfloat16* __restrict__ Bh, const __nv_bfloat16* __restrict__ Bl,
    const float* __restrict__ bias, int lda, int kstages)
{
    extern __shared__ __nv_bfloat16 smem[];
    unsigned sbase = (unsigned)__cvta_generic_to_shared(smem);

    int tid = threadIdx.x;
    int m0 = blockIdx.x * 128, n0 = blockIdx.y * 128;
    int kbase = blockIdx.z * kstages * 64;
    int warp = tid >> 5, lane = tid & 31;
    int wm = warp >> 1, wn = warp & 1;

    float acc[2][8][4];
#pragma unroll
    for (int i = 0; i < 2; i++)
#pragma unroll
        for (int j = 0; j < 8; j++)
#pragma unroll
            for (int t = 0; t < 4; t++) acc[i][j][t] = 0.f;

    int ar = tid >> 1, acu = (tid & 1) * 4;
    int br = tid >> 2, bcu = (tid & 3) * 4;
    int okA = (MODE == 0) || (m0 + ar < OD);
    int zsA = okA ? 16 : 0;
    unsigned sA0 = sbase + 2u * (unsigned)(ar * AS_STRIDE + acu * 8);
    unsigned sB0 = sbase + 2u * (unsigned)(BS_OFF + br * BS_STRIDE + bcu * 8);

    int lrow = ((lane >> 3) & 1) * 8 + (lane & 7);
    int lcol = (lane >> 4) * 8;

    const __nv_bfloat16* gAh0 = Ah + (size_t)(m0 + ar) * lda + acu * 8;
    const __nv_bfloat16* gAl0 = Al + (size_t)(m0 + ar) * lda + acu * 8;
    const __nv_bfloat16* gBh0 = Bh + (size_t)br * BB + n0 + bcu * 8;
    const __nv_bfloat16* gBl0 = Bl + (size_t)br * BB + n0 + bcu * 8;

    auto issue = [&](int st) {
        int kg = kbase + st * 64;
        unsigned off = (st & 1) * (unsigned)STG_BYTES;
        const __nv_bfloat16* gAh = gAh0 + kg;
        const __nv_bfloat16* gAl = gAl0 + kg;
        const __nv_bfloat16* gBh = gBh0 + (size_t)kg * BB;
        const __nv_bfloat16* gBl = gBl0 + (size_t)kg * BB;
#pragma unroll
        for (int j = 0; j < 4; j++) {
            cpa16(sA0 + off + j * 16, gAh + j * 8, zsA);
            cpa16(sA0 + off + 2 * AS_PLANE + j * 16, gAl + j * 8, zsA);
            cpa16(sB0 + off + j * 16, gBh + j * 8, 16);
            cpa16(sB0 + off + 2 * BS_PLANE + j * 16, gBl + j * 8, 16);
        }
        cpa_commit();
    };

    issue(0);
    for (int st = 0; st < kstages; st++) {
        if (st + 1 < kstages) issue(st + 1);
        if (st + 1 < kstages) cpa_wait1(); else cpa_wait0();
        __syncthreads();
        unsigned off = (st & 1) * (unsigned)STG_BYTES;

#pragma unroll
        for (int ks = 0; ks < 4; ks++) {
            int ks16 = ks * 16;
            unsigned a_h[2][4], a_l[2][4];
#pragma unroll
            for (int mt = 0; mt < 2; mt++) {
                unsigned aaddr = sbase + off +
                    2u * (unsigned)((wm * 32 + mt * 16 + lrow) * AS_STRIDE + ks16 + lcol);
                ldsm4(a_h[mt], aaddr);
                ldsm4(a_l[mt], aaddr + 2 * AS_PLANE);
            }
#pragma unroll
            for (int np = 0; np < 4; np++) {
                unsigned b_h[4], b_l[4];
                unsigned baddr = sbase + off +
                    2u * (unsigned)(BS_OFF + (ks16 + lrow) * BS_STRIDE + wn * 64 + np * 16 + lcol);
                ldsm4t(b_h, baddr);
                ldsm4t(b_l, baddr + 2 * BS_PLANE);
#pragma unroll
                for (int mt = 0; mt < 2; mt++) {
                    mma_bf16(acc[mt][np * 2],     a_h[mt], b_h);
                    mma_bf16(acc[mt][np * 2],     a_l[mt], b_h);
                    mma_bf16(acc[mt][np * 2],     a_h[mt], b_l);
                    mma_bf16(acc[mt][np * 2 + 1], a_h[mt], b_h + 2);
                    mma_bf16(acc[mt][np * 2 + 1], a_l[mt], b_h + 2);
                    mma_bf16(acc[mt][np * 2 + 1], a_h[mt], b_l + 2);
                }
            }
        }
        __syncthreads();
    }

    int g = lane >> 2, ti = lane & 3;
#pragma unroll
    for (int mt = 0; mt < 2; mt++) {
#pragma unroll
        for (int nt = 0; nt < 8; nt++) {
            float* c = acc[mt][nt];
            int row = m0 + wm * 32 + mt * 16 + g;
            int col = n0 + wn * 64 + nt * 8 + 2 * ti;
            if (MODE == 0) {
                float bv0 = bias[row], bv1 = bias[row + 8];
                *(float2*)(g_xp + (size_t)row * BB + col) = make_float2(c[0] + bv0, c[1] + bv0);
                *(float2*)(g_xp + (size_t)(row + 8) * BB + col) = make_float2(c[2] + bv1, c[3] + bv1);
            } else {
                float* base = g_part + (size_t)(blockIdx.z * BB) * ODP;
                base[(size_t)col * ODP + row] = c[0];
                base[(size_t)(col + 1) * ODP + row] = c[1];
                base[(size_t)col * ODP + row + 8] = c[2];
                base[(size_t)(col + 1) * ODP + row + 8] = c[3];
            }
        }
    }
}

// ---------------- step0 ----------------
__global__ __launch_bounds__(256) void step0_kernel() {
    int i = blockIdx.x * 256 + threadIdx.x;
    g_h[0][i] = tanh_acc(g_xp[i]);
}

// ---------------- stencil step: plane sweep, rotating accumulators ----------------
// tile 4y x 2z x 24x x 16b; 256 threads = q(8) x ry(4) x rz(2) x xq(4); 6 x-outputs/thread
#define PLANE(PI, A0, A1, A2, C2, C1, C0)                                         \
    {                                                                             \
        float2 v[9];                                                              \
        _Pragma("unroll")                                                         \
        for (int r = 0; r < 9; r++)                                               \
            v[r] = *(const float2*)(sh + roff[r] + (x0 + (PI)) * SITE);           \
        if (C0) {                                                                 \
            float2 a = xpv[PI];                                                   \
            _Pragma("unroll")                                                     \
            for (int r = 0; r < 9; r++) {                                         \
                float w = wrow[r * 24 + (x0 + (PI))];                             \
                a.x = fmaf(w, v[r].x, a.x); a.y = fmaf(w, v[r].y, a.y);           \
            }                                                                     \
            A2 = a;                                                               \
        }                                                                         \
        if (C1) {                                                                 \
            _Pragma("unroll")                                                     \
            for (int r = 0; r < 9; r++) {                                         \
                float w = wrow[216 + r * 24 + (x0 + (PI) - 1)];                   \
                A1.x = fmaf(w, v[r].x, A1.x); A1.y = fmaf(w, v[r].y, A1.y);       \
            }                                                                     \
        }                                                                         \
        if (C2) {                                                                 \
            _Pragma("unroll")                                                     \
            for (int r = 0; r < 9; r++) {                                         \
                float w = wrow[432 + r * 24 + (x0 + (PI) - 2)];                   \
                A0.x = fmaf(w, v[r].x, A0.x); A0.y = fmaf(w, v[r].y, A0.y);       \
            }                                                                     \
            float2 o;                                                             \
            o.x = tanh_acc(A0.x); o.y = tanh_acc(A0.y);                           \
            *(float2*)(horow + ((PI) - 2) * BB) = o;                              \
        }                                                                         \
    }

__global__ __launch_bounds__(256, 3) void step_kernel(int src, const float* __restrict__ Wl) {
    const float* __restrict__ hin = g_h[src];
    float* __restrict__ hout = g_h[src ^ 1];

    extern __shared__ float dyn[];
    float* sh  = dyn;            // halo [4z][6y(+pad)][26x][16b]
    float* wsh = dyn + HALO_F;   // weights [8 rows][3 c][9 r][24 x]

    int tid = threadIdx.x;
    int y0 = blockIdx.x * 4;
    int z0 = blockIdx.y * 2;
    int b0 = blockIdx.z * 16;

    // halo: 4z x 6y x 26x = 624 sites x 4 float4
    for (int i = tid; i < 624 * 4; i += 256) {
        int q4 = i & 3; int site = i >> 2;
        int xx = site % 26; int t2 = site / 26;
        int yy = t2 % 6;    int zz = t2 / 6;
        int gx = xx - 1, gy = y0 + yy - 1, gz = z0 + zz - 1;
        float4 v = make_float4(0.f, 0.f, 0.f, 0.f);
        if ((unsigned)gx < (unsigned)CUBE && (unsigned)gy < (unsigned)CUBE &&
            (unsigned)gz < (unsigned)CUBE)
            v = *(const float4*)(hin + (size_t)(gz * 576 + gy * 24 + gx) * BB + b0 + q4 * 4);
        *(float4*)(sh + zz * H_ZS + yy * H_YS + xx * SITE + q4 * 4) = v;
    }
    // weights transposed: k = r*3 + c -> dest row*648 + c*216 + r*24 + x
    for (int j = tid; j < 8 * 648; j += 256) {
        int row = j / 648, t = j % 648;
        int x = t / 27, k = t % 27;
        int c = k - (k / 3) * 3, r = k / 3;
        int nr = (z0 + (row >> 2)) * 576 + (y0 + (row & 3)) * 24;
        wsh[row * W_RS + c * 216 + r * 24 + x] = Wl[(size_t)(nr + x) * 27 + k];
    }
    __syncthreads();

    int q  = tid & 7;
    int ry = (tid >> 3) & 3;
    int rz = (tid >> 5) & 1;
    int xq = tid >> 6;
    int x0 = xq * 6;

    int roff[9];
#pragma unroll
    for (int dz = 0; dz < 3; dz++)
#pragma unroll
        for (int dy = 0; dy < 3; dy++)
            roff[dz * 3 + dy] = (rz + dz) * H_ZS + (ry + dy) * H_YS + q * 2;

    const float* wrow = wsh + (rz * 4 + ry) * W_RS;
    int nrow = (z0 + rz) * 576 + (y0 + ry) * 24 + x0;
    const float* xprow = g_xp + (size_t)nrow * BB + b0 + q * 2;
    float* horow = hout + (size_t)nrow * BB + b0 + q * 2;

    float2 xpv[8];
#pragma unroll
    for (int j = 0; j < 6; j++) xpv[j] = *(const float2*)(xprow + j * BB);
    xpv[6] = xpv[7] = make_float2(0.f, 0.f);

    float2 accA, accB, accC;
    PLANE(0, accA, accB, accC, 0, 0, 1)
    PLANE(1, accB, accC, accA, 0, 1, 1)
    PLANE(2, accC, accA, accB, 1, 1, 1)
    PLANE(3, accA, accB, accC, 1, 1, 1)
    PLANE(4, accB, accC, accA, 1, 1, 1)
    PLANE(5, accC, accA, accB, 1, 1, 1)
    PLANE(6, accA, accB, accC, 1, 1, 0)
    PLANE(7, accB, accC, accA, 1, 0, 0)
}

// ---------------- split h ----------------
__global__ __launch_bounds__(256) void split_h_kernel() {
    int i = blockIdx.x * 256 + threadIdx.x;
    float v = g_h[1][i];
    __nv_bfloat16 h = __float2bfloat16_rn(v);
    g_hH[i] = h;
    g_hL[i] = __float2bfloat16_rn(v - __bfloat162float(h));
}

// ---------------- reduce ----------------
__global__ __launch_bounds__(256) void reduce_kernel(const float* __restrict__ bo,
                                                     float* __restrict__ out) {
    int idx = blockIdx.x * 256 + threadIdx.x;
    if (idx >= BB * OD) return;
    int b = idx / OD, o = idx % OD;
    float s = bo[o];
#pragma unroll
    for (int sk = 0; sk < SK; sk++)
        s += g_part[(size_t)(sk * BB + b) * ODP + o];
    out[b * OD + o] = s;
}

// ---------------- launch ----------------
extern "C" void kernel_launch(void* const* d_in, const int* in_sizes, int n_in,
                              void* d_out, int out_size) {
    const float* x   = (const float*)d_in[0];
    const float* Wi  = (const float*)d_in[1];
    const float* bi  = (const float*)d_in[2];
    const float* Wl  = (const float*)d_in[3];
    const float* Wo  = (const float*)d_in[4];
    const float* bo  = (const float*)d_in[5];
    float* out = (float*)d_out;

    cudaFuncSetAttribute(step_kernel, cudaFuncAttributeMaxDynamicSharedMemorySize, STEP_SMEM);
    cudaFuncSetAttribute(mma_gemm<0>, cudaFuncAttributeMaxDynamicSharedMemorySize, GEMM_SMEM);
    cudaFuncSetAttribute(mma_gemm<1>, cudaFuncAttributeMaxDynamicSharedMemorySize, GEMM_SMEM);

    __nv_bfloat16 *winH, *winL, *woH, *woL, *xtH, *xtL, *hH, *hL;
    cudaGetSymbolAddress((void**)&winH, g_WinH);
    cudaGetSymbolAddress((void**)&winL, g_WinL);
    cudaGetSymbolAddress((void**)&woH, g_WoH);
    cudaGetSymbolAddress((void**)&woL, g_WoL);
    cudaGetSymbolAddress((void**)&xtH, g_xTH);
    cudaGetSymbolAddress((void**)&xtL, g_xTL);
    cudaGetSymbolAddress((void**)&hH, g_hH);
    cudaGetSymbolAddress((void**)&hL, g_hL);

    split_kernel<<<(NN * DIM / 4 + 255) / 256, 256>>>(Wi, winH, winL, NN * DIM / 4);
    split_xT_kernel<<<dim3(BB / 32, DIM / 32), 256>>>(x);
    split_kernel<<<(OD * NN / 4 + 255) / 256, 256>>>(Wo, woH, woL, OD * NN / 4);

    mma_gemm<0><<<dim3(NN / 128, BB / 128, 1), 256, GEMM_SMEM>>>(
        winH, winL, xtH, xtL, bi, DIM, DIM / 64);

    step0_kernel<<<NN * BB / 256, 256>>>();

    int src = 0;
    for (int s = 0; s < 29; s++) {
        step_kernel<<<dim3(CUBE / 4, CUBE / 2, BB / 16), 256, STEP_SMEM>>>(src, Wl);
        src ^= 1;
    }

    split_h_kernel<<<NN * BB / 256, 256>>>();

    mma_gemm<1><<<dim3(ODP / 128, BB / 128, SK), 256, GEMM_SMEM>>>(
        woH, woL, hH, hL, nullptr, NN, KC / 64);
    reduce_kernel<<<(BB * OD + 255) / 256, 256>>>(bo, out);
}

// round 9
// speedup vs baseline: 2.8516x; 2.8516x over previous
#include <cuda_runtime.h>
#include <cuda_bf16.h>

#define NN   13824
#define BB   256
#define DIM  512
#define OD   1000
#define ODP  1024
#define SK   9
#define KC   (NN / SK)
#define CUBE 24

// ---- stencil smem geometry (R6 tile: 8y x 2z x 24x x 16b) ----
#define H_YS 432                   // 26*16 + 16 pad
#define H_ZS (10 * H_YS)           // 4320
#define HALO_F (4 * H_ZS)          // 17280 floats
#define WROW 676                   // 24*28 + 4; %32=4 -> distinct broadcast banks
#define WSH_F (16 * WROW)          // 10816
#define STEP_SMEM ((HALO_F + WSH_F) * 4)   // 112384 B -> 2 CTA/SM

// ---- GEMM smem geometry ----
#define AS_STRIDE 72
#define BS_STRIDE 136
#define AS_PLANE  (128 * AS_STRIDE)
#define BS_PLANE  (64 * BS_STRIDE)
#define BS_OFF    (2 * AS_PLANE)
#define STG_UNITS (2 * AS_PLANE + 2 * BS_PLANE)
#define STG_BYTES (STG_UNITS * 2)
#define GEMM_SMEM (2 * STG_BYTES)

// ---------------- device scratch ----------------
__device__ float g_xp[NN * BB];
__device__ float g_h[2][NN * BB];
__device__ float g_part[SK * BB * ODP];
__device__ float g_Wp[NN * 28];               // padded weights [n][28]
__device__ __nv_bfloat16 g_WinH[NN * DIM], g_WinL[NN * DIM];
__device__ __nv_bfloat16 g_xTH[DIM * BB],  g_xTL[DIM * BB];
__device__ __nv_bfloat16 g_WoH[OD * NN],   g_WoL[OD * NN];
__device__ __nv_bfloat16 g_hH[NN * BB],    g_hL[NN * BB];

__device__ __forceinline__ float tanh_acc(float x) {
    x = fminf(15.0f, fmaxf(-15.0f, x));
    float e = __expf(2.0f * x);
    return __fdividef(e - 1.0f, e + 1.0f);
}

// ---------------- conversions / prep ----------------
__global__ __launch_bounds__(256) void split_kernel(const float* __restrict__ s,
                                                    __nv_bfloat16* __restrict__ hi,
                                                    __nv_bfloat16* __restrict__ lo, int n4) {
    int i = blockIdx.x * 256 + threadIdx.x;
    if (i >= n4) return;
    float4 v = *(const float4*)(s + i * 4);
    __nv_bfloat16 h0 = __float2bfloat16_rn(v.x), h1 = __float2bfloat16_rn(v.y);
    __nv_bfloat16 h2 = __float2bfloat16_rn(v.z), h3 = __float2bfloat16_rn(v.w);
    __nv_bfloat162 H0 = {h0, h1}, H1 = {h2, h3};
    *(__nv_bfloat162*)(hi + i * 4) = H0;
    *(__nv_bfloat162*)(hi + i * 4 + 2) = H1;
    __nv_bfloat162 L0 = {__float2bfloat16_rn(v.x - __bfloat162float(h0)),
                         __float2bfloat16_rn(v.y - __bfloat162float(h1))};
    __nv_bfloat162 L1 = {__float2bfloat16_rn(v.z - __bfloat162float(h2)),
                         __float2bfloat16_rn(v.w - __bfloat162float(h3))};
    *(__nv_bfloat162*)(lo + i * 4) = L0;
    *(__nv_bfloat162*)(lo + i * 4 + 2) = L1;
}

__global__ __launch_bounds__(256) void split_xT_kernel(const float* __restrict__ x) {
    __shared__ float t[32][33];
    int bx = blockIdx.x * 32, kx = blockIdx.y * 32;
    int tx = threadIdx.x & 31, ty = threadIdx.x >> 5;
#pragma unroll
    for (int j = ty; j < 32; j += 8)
        t[j][tx] = x[(size_t)(bx + j) * DIM + kx + tx];
    __syncthreads();
#pragma unroll
    for (int j = ty; j < 32; j += 8) {
        float v = t[tx][j];
        __nv_bfloat16 h = __float2bfloat16_rn(v);
        size_t o = (size_t)(kx + j) * BB + bx + tx;
        g_xTH[o] = h;
        g_xTL[o] = __float2bfloat16_rn(v - __bfloat162float(h));
    }
}

__global__ __launch_bounds__(256) void wprep_kernel(const float* __restrict__ Wl) {
    int i = blockIdx.x * 256 + threadIdx.x;
    if (i >= NN * 28) return;
    int n = i / 28, k = i - n * 28;
    g_Wp[i] = (k < 27) ? Wl[n * 27 + k] : 0.f;
}

// ---------------- mma helpers ----------------
__device__ __forceinline__ void ldsm4(unsigned* r, unsigned addr) {
    asm volatile("ldmatrix.sync.aligned.m8n8.x4.shared.b16 {%0,%1,%2,%3},[%4];"
                 : "=r"(r[0]), "=r"(r[1]), "=r"(r[2]), "=r"(r[3]) : "r"(addr));
}
__device__ __forceinline__ void ldsm4t(unsigned* r, unsigned addr) {
    asm volatile("ldmatrix.sync.aligned.m8n8.x4.trans.shared.b16 {%0,%1,%2,%3},[%4];"
                 : "=r"(r[0]), "=r"(r[1]), "=r"(r[2]), "=r"(r[3]) : "r"(addr));
}
__device__ __forceinline__ void mma_bf16(float* c, const unsigned* a, const unsigned* b) {
    asm volatile("mma.sync.aligned.m16n8k16.row.col.f32.bf16.bf16.f32 "
                 "{%0,%1,%2,%3},{%4,%5,%6,%7},{%8,%9},{%0,%1,%2,%3};"
                 : "+f"(c[0]), "+f"(c[1]), "+f"(c[2]), "+f"(c[3])
                 : "r"(a[0]), "r"(a[1]), "r"(a[2]), "r"(a[3]), "r"(b[0]), "r"(b[1]));
}
__device__ __forceinline__ void cpa16(unsigned s, const void* g, int zs) {
    asm volatile("cp.async.ca.shared.global [%0],[%1],16,%2;" :: "r"(s), "l"(g), "r"(zs));
}
__device__ __forceinline__ void cpa_commit() {
    asm volatile("cp.async.commit_group;" ::: "memory");
}
__device__ __forceinline__ void cpa_wait1() {
    asm volatile("cp.async.wait_group 1;" ::: "memory");
}
__device__ __forceinline__ void cpa_wait0() {
    asm volatile("cp.async.wait_group 0;" ::: "memory");
}

// ---------------- split-precision bf16 MMA GEMM ----------------
// MODE 0: xproj -> g_xp (+bias) AND g_h[0] = tanh(g_xp)
// MODE 1: outgemm -> g_part
template<int MODE>
__global__ __launch_bounds__(256) void mma_gemm(
    const __nv_bfloat16* __restrict__ Ah, const __nv_bfloat16* __restrict__ Al,
    const __nv_bfloat16* __restrict__ Bh, const __nv_bfloat16* __restrict__ Bl,
    const float* __restrict__ bias, int lda, int kstages)
{
    extern __shared__ __nv_bfloat16 smem[];
    unsigned sbase = (unsigned)__cvta_generic_to_shared(smem);

    int tid = threadIdx.x;
    int m0 = blockIdx.x * 128, n0 = blockIdx.y * 128;
    int kbase = blockIdx.z * kstages * 64;
    int warp = tid >> 5, lane = tid & 31;
    int wm = warp >> 1, wn = warp & 1;

    float acc[2][8][4];
#pragma unroll
    for (int i = 0; i < 2; i++)
#pragma unroll
        for (int j = 0; j < 8; j++)
#pragma unroll
            for (int t = 0; t < 4; t++) acc[i][j][t] = 0.f;

    int ar = tid >> 1, acu = (tid & 1) * 4;
    int br = tid >> 2, bcu = (tid & 3) * 4;
    int okA = (MODE == 0) || (m0 + ar < OD);
    int zsA = okA ? 16 : 0;
    unsigned sA0 = sbase + 2u * (unsigned)(ar * AS_STRIDE + acu * 8);
    unsigned sB0 = sbase + 2u * (unsigned)(BS_OFF + br * BS_STRIDE + bcu * 8);

    int lrow = ((lane >> 3) & 1) * 8 + (lane & 7);
    int lcol = (lane >> 4) * 8;

    const __nv_bfloat16* gAh0 = Ah + (size_t)(m0 + ar) * lda + acu * 8;
    const __nv_bfloat16* gAl0 = Al + (size_t)(m0 + ar) * lda + acu * 8;
    const __nv_bfloat16* gBh0 = Bh + (size_t)br * BB + n0 + bcu * 8;
    const __nv_bfloat16* gBl0 = Bl + (size_t)br * BB + n0 + bcu * 8;

    auto issue = [&](int st) {
        int kg = kbase + st * 64;
        unsigned off = (st & 1) * (unsigned)STG_BYTES;
        const __nv_bfloat16* gAh = gAh0 + kg;
        const __nv_bfloat16* gAl = gAl0 + kg;
        const __nv_bfloat16* gBh = gBh0 + (size_t)kg * BB;
        const __nv_bfloat16* gBl = gBl0 + (size_t)kg * BB;
#pragma unroll
        for (int j = 0; j < 4; j++) {
            cpa16(sA0 + off + j * 16, gAh + j * 8, zsA);
            cpa16(sA0 + off + 2 * AS_PLANE + j * 16, gAl + j * 8, zsA);
            cpa16(sB0 + off + j * 16, gBh + j * 8, 16);
            cpa16(sB0 + off + 2 * BS_PLANE + j * 16, gBl + j * 8, 16);
        }
        cpa_commit();
    };

    issue(0);
    for (int st = 0; st < kstages; st++) {
        if (st + 1 < kstages) issue(st + 1);
        if (st + 1 < kstages) cpa_wait1(); else cpa_wait0();
        __syncthreads();
        unsigned off = (st & 1) * (unsigned)STG_BYTES;

#pragma unroll
        for (int ks = 0; ks < 4; ks++) {
            int ks16 = ks * 16;
            unsigned a_h[2][4], a_l[2][4];
#pragma unroll
            for (int mt = 0; mt < 2; mt++) {
                unsigned aaddr = sbase + off +
                    2u * (unsigned)((wm * 32 + mt * 16 + lrow) * AS_STRIDE + ks16 + lcol);
                ldsm4(a_h[mt], aaddr);
                ldsm4(a_l[mt], aaddr + 2 * AS_PLANE);
            }
#pragma unroll
            for (int np = 0; np < 4; np++) {
                unsigned b_h[4], b_l[4];
                unsigned baddr = sbase + off +
                    2u * (unsigned)(BS_OFF + (ks16 + lrow) * BS_STRIDE + wn * 64 + np * 16 + lcol);
                ldsm4t(b_h, baddr);
                ldsm4t(b_l, baddr + 2 * BS_PLANE);
#pragma unroll
                for (int mt = 0; mt < 2; mt++) {
                    mma_bf16(acc[mt][np * 2],     a_h[mt], b_h);
                    mma_bf16(acc[mt][np * 2],     a_l[mt], b_h);
                    mma_bf16(acc[mt][np * 2],     a_h[mt], b_l);
                    mma_bf16(acc[mt][np * 2 + 1], a_h[mt], b_h + 2);
                    mma_bf16(acc[mt][np * 2 + 1], a_l[mt], b_h + 2);
                    mma_bf16(acc[mt][np * 2 + 1], a_h[mt], b_l + 2);
                }
            }
        }
        __syncthreads();
    }

    int g = lane >> 2, ti = lane & 3;
#pragma unroll
    for (int mt = 0; mt < 2; mt++) {
#pragma unroll
        for (int nt = 0; nt < 8; nt++) {
            float* c = acc[mt][nt];
            int row = m0 + wm * 32 + mt * 16 + g;
            int col = n0 + wn * 64 + nt * 8 + 2 * ti;
            if (MODE == 0) {
                float bv0 = bias[row], bv1 = bias[row + 8];
                float v0 = c[0] + bv0, v1 = c[1] + bv0;
                float v2 = c[2] + bv1, v3 = c[3] + bv1;
                *(float2*)(g_xp + (size_t)row * BB + col) = make_float2(v0, v1);
                *(float2*)(g_xp + (size_t)(row + 8) * BB + col) = make_float2(v2, v3);
                *(float2*)(g_h[0] + (size_t)row * BB + col) =
                    make_float2(tanh_acc(v0), tanh_acc(v1));
                *(float2*)(g_h[0] + (size_t)(row + 8) * BB + col) =
                    make_float2(tanh_acc(v2), tanh_acc(v3));
            } else {
                float* base = g_part + (size_t)(blockIdx.z * BB) * ODP;
                base[(size_t)col * ODP + row] = c[0];
                base[(size_t)(col + 1) * ODP + row] = c[1];
                base[(size_t)col * ODP + row + 8] = c[2];
                base[(size_t)(col + 1) * ODP + row + 8] = c[3];
            }
        }
    }
}

// ---------------- stencil step (R6 core, cp.async staging) ----------------
#define STENCIL_X(XI, P0, P1, P2)                                              \
    {                                                                          \
        const int x = x0 + (XI);                                               \
        float wv[28];                                                          \
        _Pragma("unroll")                                                      \
        for (int t = 0; t < 7; t++)                                            \
            *(float4*)(wv + t * 4) = *(const float4*)(wq + x * 28 + t * 4);    \
        _Pragma("unroll")                                                      \
        for (int r = 0; r < 9; r++)                                            \
            P2[r] = *(const float2*)(sh + roff[r] + (x + 2) * 16);             \
        float2 s0 = accv[XI];                                                  \
        float2 s1 = make_float2(0.f, 0.f);                                     \
        float2 s2 = make_float2(0.f, 0.f);                                     \
        _Pragma("unroll")                                                      \
        for (int r = 0; r < 9; r++) {                                          \
            float w0 = wv[r * 3 + 0], w1 = wv[r * 3 + 1], w2 = wv[r * 3 + 2];  \
            s0.x = fmaf(w0, P0[r].x, s0.x); s0.y = fmaf(w0, P0[r].y, s0.y);    \
            s1.x = fmaf(w1, P1[r].x, s1.x); s1.y = fmaf(w1, P1[r].y, s1.y);    \
            s2.x = fmaf(w2, P2[r].x, s2.x); s2.y = fmaf(w2, P2[r].y, s2.y);    \
        }                                                                      \
        float2 o;                                                              \
        o.x = tanh_acc(s0.x + (s1.x + s2.x));                                  \
        o.y = tanh_acc(s0.y + (s1.y + s2.y));                                  \
        if (FINAL) {                                                           \
            __nv_bfloat16 hh0 = __float2bfloat16_rn(o.x);                      \
            __nv_bfloat16 hh1 = __float2bfloat16_rn(o.y);                      \
            __nv_bfloat162 HH = {hh0, hh1};                                    \
            __nv_bfloat162 LL = {                                              \
                __float2bfloat16_rn(o.x - __bfloat162float(hh0)),              \
                __float2bfloat16_rn(o.y - __bfloat162float(hh1))};             \
            *(__nv_bfloat162*)(hHrow + (XI) * BB) = HH;                        \
            *(__nv_bfloat162*)(hLrow + (XI) * BB) = LL;                        \
        } else {                                                               \
            *(float2*)(horow + (XI) * BB) = o;                                 \
        }                                                                      \
    }

template<int FINAL>
__global__ __launch_bounds__(256, 2) void step_kernel(int src) {
    const float* __restrict__ hin = g_h[src];
    float* __restrict__ hout = g_h[src ^ 1];

    extern __shared__ float dyn[];
    float* sh  = dyn;
    float* wsh = dyn + HALO_F;
    unsigned sb = (unsigned)__cvta_generic_to_shared(dyn);

    int tid = threadIdx.x;
    int lane = tid & 31, w = tid >> 5;
    int y0 = blockIdx.x * 8;
    int z0 = blockIdx.y * 2;
    int b0 = blockIdx.z * 16;

    // ---- halo staging: 40 site-rows (4z x 10y), 8 warps x 5 rows, cp.async zfill ----
#pragma unroll
    for (int j = 0; j < 5; j++) {
        int row = w * 5 + j;
        int zz = row / 10, yy = row - zz * 10;
        int gz = z0 + zz - 1, gy = y0 + yy - 1;
        bool zyok = ((unsigned)gz < (unsigned)CUBE) && ((unsigned)gy < (unsigned)CUBE);
        const float* srow = hin + ((size_t)(gz * 576 + gy * 24 - 1) * BB + b0);
        unsigned drow = sb + 4u * (unsigned)(zz * H_ZS + yy * H_YS);
#pragma unroll
        for (int k = 0; k < 4; k++) {
            int f4 = lane + k * 32;
            if (f4 < 104) {
                int xx = f4 >> 2, q = f4 & 3;
                int zs = (zyok && (unsigned)(xx - 1) < (unsigned)CUBE) ? 16 : 0;
                cpa16(drow + (unsigned)(xx * 16 + q * 4) * 4u,
                      srow + (size_t)xx * BB + q * 4, zs);
            }
        }
    }
    // ---- weight staging: 16 rows x 168 float4, 8 warps x 2 rows, contiguous ----
#pragma unroll
    for (int j = 0; j < 2; j++) {
        int row = w * 2 + j;
        int nr = (z0 + (row >> 3)) * 576 + (y0 + (row & 7)) * 24;
        const float* wsrc = g_Wp + (size_t)nr * 28;
        unsigned wdst = sb + 4u * (unsigned)(HALO_F + row * WROW);
#pragma unroll
        for (int k = 0; k < 6; k++) {
            int f4 = lane + k * 32;
            if (f4 < 168) cpa16(wdst + f4 * 16, wsrc + f4 * 4, 16);
        }
    }
    cpa_commit();
    cpa_wait0();
    __syncthreads();

    int q  = tid & 7;
    int ry = (tid >> 3) & 7;
    int rz = (tid >> 6) & 1;
    int xq = tid >> 7;
    int x0 = xq * 12;

    int roff[9];
#pragma unroll
    for (int dz = 0; dz < 3; dz++)
#pragma unroll
        for (int dy = 0; dy < 3; dy++)
            roff[dz * 3 + dy] = (rz + dz) * H_ZS + (ry + dy) * H_YS + q * 2;

    float2 A[9], B[9], C[9];
#pragma unroll
    for (int r = 0; r < 9; r++) {
        A[r] = *(const float2*)(sh + roff[r] + x0 * 16);
        B[r] = *(const float2*)(sh + roff[r] + (x0 + 1) * 16);
    }

    int nrow = (z0 + rz) * 576 + (y0 + ry) * 24 + x0;
    const float* wq = wsh + (rz * 8 + ry) * WROW;
    const float* xprow = g_xp + (size_t)nrow * BB + b0 + q * 2;
    float* horow = hout + (size_t)nrow * BB + b0 + q * 2;
    __nv_bfloat16* hHrow = g_hH + (size_t)nrow * BB + b0 + q * 2;
    __nv_bfloat16* hLrow = g_hL + (size_t)nrow * BB + b0 + q * 2;

    float2 accv[12];
#pragma unroll
    for (int j = 0; j < 6; j++) accv[j] = *(const float2*)(xprow + j * BB);

    STENCIL_X(0, A, B, C)
    STENCIL_X(1, B, C, A)
    STENCIL_X(2, C, A, B)

#pragma unroll
    for (int j = 6; j < 12; j++) accv[j] = *(const float2*)(xprow + j * BB);

    STENCIL_X(3, A, B, C)
    STENCIL_X(4, B, C, A)
    STENCIL_X(5, C, A, B)
    STENCIL_X(6, A, B, C)
    STENCIL_X(7, B, C, A)
    STENCIL_X(8, C, A, B)
    STENCIL_X(9, A, B, C)
    STENCIL_X(10, B, C, A)
    STENCIL_X(11, C, A, B)
}

// ---------------- reduce (float4) ----------------
__global__ __launch_bounds__(256) void reduce_kernel(const float* __restrict__ bo,
                                                     float* __restrict__ out) {
    int idx = blockIdx.x * 256 + threadIdx.x;
    if (idx >= BB * OD / 4) return;
    int b = idx / 250, o4 = idx - b * 250;
    float4 s = *(const float4*)(bo + o4 * 4);
#pragma unroll
    for (int sk = 0; sk < SK; sk++) {
        float4 p = *(const float4*)(g_part + (size_t)(sk * BB + b) * ODP + o4 * 4);
        s.x += p.x; s.y += p.y; s.z += p.z; s.w += p.w;
    }
    *(float4*)(out + (size_t)b * OD + o4 * 4) = s;
}

// ---------------- launch ----------------
extern "C" void kernel_launch(void* const* d_in, const int* in_sizes, int n_in,
                              void* d_out, int out_size) {
    const float* x   = (const float*)d_in[0];
    const float* Wi  = (const float*)d_in[1];
    const float* bi  = (const float*)d_in[2];
    const float* Wl  = (const float*)d_in[3];
    const float* Wo  = (const float*)d_in[4];
    const float* bo  = (const float*)d_in[5];
    float* out = (float*)d_out;

    cudaFuncSetAttribute(step_kernel<0>, cudaFuncAttributeMaxDynamicSharedMemorySize, STEP_SMEM);
    cudaFuncSetAttribute(step_kernel<1>, cudaFuncAttributeMaxDynamicSharedMemorySize, STEP_SMEM);
    cudaFuncSetAttribute(mma_gemm<0>, cudaFuncAttributeMaxDynamicSharedMemorySize, GEMM_SMEM);
    cudaFuncSetAttribute(mma_gemm<1>, cudaFuncAttributeMaxDynamicSharedMemorySize, GEMM_SMEM);

    __nv_bfloat16 *winH, *winL, *woH, *woL, *xtH, *xtL, *hH, *hL;
    cudaGetSymbolAddress((void**)&winH, g_WinH);
    cudaGetSymbolAddress((void**)&winL, g_WinL);
    cudaGetSymbolAddress((void**)&woH, g_WoH);
    cudaGetSymbolAddress((void**)&woL, g_WoL);
    cudaGetSymbolAddress((void**)&xtH, g_xTH);
    cudaGetSymbolAddress((void**)&xtL, g_xTL);
    cudaGetSymbolAddress((void**)&hH, g_hH);
    cudaGetSymbolAddress((void**)&hL, g_hL);

    split_kernel<<<(NN * DIM / 4 + 255) / 256, 256>>>(Wi, winH, winL, NN * DIM / 4);
    split_xT_kernel<<<dim3(BB / 32, DIM / 32), 256>>>(x);
    split_kernel<<<(OD * NN / 4 + 255) / 256, 256>>>(Wo, woH, woL, OD * NN / 4);
    wprep_kernel<<<(NN * 28 + 255) / 256, 256>>>(Wl);

    mma_gemm<0><<<dim3(NN / 128, BB / 128, 1), 256, GEMM_SMEM>>>(
        winH, winL, xtH, xtL, bi, DIM, DIM / 64);

    int src = 0;
    for (int s = 0; s < 28; s++) {
        step_kernel<0><<<dim3(CUBE / 8, CUBE / 2, BB / 16), 256, STEP_SMEM>>>(src);
        src ^= 1;
    }
    step_kernel<1><<<dim3(CUBE / 8, CUBE / 2, BB / 16), 256, STEP_SMEM>>>(src);

    mma_gemm<1><<<dim3(ODP / 128, BB / 128, SK), 256, GEMM_SMEM>>>(
        woH, woL, hH, hL, nullptr, NN, KC / 64);
    reduce_kernel<<<(BB * OD / 4 + 255) / 256, 256>>>(bo, out);
}